// round 6
// baseline (speedup 1.0000x reference)
#include <cuda_runtime.h>
#include <cuda_fp16.h>
#include <math.h>

#define Bb 16
#define Hh 512
#define Ww 512
#define HW (Hh*Ww)
#define BHW (Bb*HW)
#define Lsteps 10

// ---- scratch in device globals (no allocation allowed) ----
__device__ float   d_res[10 * BHW];     // residuals[1..10] fp32 master (slot k = residuals[k+1])
__device__ __half  d_res16[10 * BHW];   // fp16 shadow for gathers
__device__ __half2 d_uA[10 * BHW];      // phi displacement ping (u = phi - id)
__device__ __half2 d_uB[10 * BHW];      // phi displacement pong
__device__ float   d_img[BHW];          // current image
__device__ float   d_t[2 * BHW];        // t = blurH(-res*grad(img)), 2 channels

// 7-tap gaussian, sigma=2 (normalized)
__device__ __constant__ float GW[7] = {
    0.070159329f, 0.131074882f, 0.190712821f, 0.216105908f,
    0.190712821f, 0.131074882f, 0.070159329f
};

// ============ velocity stage 1: t = blurH(-res * sobel(img)) ============
// Thread = one x column, 4 consecutive y rows. Rolling 3x9 img register window.
__global__ __launch_bounds__(256) void k_vel1(const float* __restrict__ img,
                                              const float* __restrict__ res,
                                              float* __restrict__ t01) {
    const int x  = blockIdx.x * 32 + threadIdx.x;
    const int y0 = (blockIdx.y * 8 + threadIdx.y) * 4;
    const int b  = blockIdx.z;
    const float* ip = img + (size_t)b * HW;
    const float* rp = res + (size_t)b * HW;

    // clamped column indices for the 9-wide img window (x-4 .. x+4)
    int xs[9];
    #pragma unroll
    for (int j = 0; j < 9; j++) xs[j] = min(max(x - 4 + j, 0), Ww - 1);

    float r0[9], r1[9], r2[9];
    {
        int ym = max(y0 - 1, 0);
        const float* pr = ip + ym * Ww;
        #pragma unroll
        for (int j = 0; j < 9; j++) r0[j] = pr[xs[j]];
        pr = ip + y0 * Ww;
        #pragma unroll
        for (int j = 0; j < 9; j++) r1[j] = pr[xs[j]];
        int yp = min(y0 + 1, Hh - 1);
        pr = ip + yp * Ww;
        #pragma unroll
        for (int j = 0; j < 9; j++) r2[j] = pr[xs[j]];
    }

    #pragma unroll
    for (int q = 0; q < 4; q++) {
        int yr = y0 + q;
        // res taps x-3..x+3 (zero-padded)
        float rr[7];
        #pragma unroll
        for (int k = 0; k < 7; k++) {
            int xc = x - 3 + k;
            rr[k] = (xc >= 0 && xc < Ww) ? rp[yr * Ww + xc] : 0.f;
        }
        float t0 = 0.f, t1 = 0.f;
        #pragma unroll
        for (int k = 0; k < 7; k++) {
            // grad at col x-3+k uses register cols k, k+1, k+2
            float gxv = (-r0[k] + r0[k + 2] - 2.f * r1[k] + 2.f * r1[k + 2]
                         - r2[k] + r2[k + 2]) * 0.125f;
            float gyv = (-r0[k] - 2.f * r0[k + 1] - r0[k + 2]
                         + r2[k] + 2.f * r2[k + 1] + r2[k + 2]) * 0.125f;
            t0 += GW[k] * (-rr[k] * gxv);
            t1 += GW[k] * (-rr[k] * gyv);
        }
        int gidx = b * HW + yr * Ww + x;
        t01[gidx]       = t0;
        t01[BHW + gidx] = t1;

        // roll img window down one row
        if (q < 3) {
            #pragma unroll
            for (int j = 0; j < 9; j++) { r0[j] = r1[j]; r1[j] = r2[j]; }
            int yn = min(yr + 2, Hh - 1);
            const float* pr = ip + yn * Ww;
            #pragma unroll
            for (int j = 0; j < 9; j++) r2[j] = pr[xs[j]];
        }
    }
}

// ============ velocity stage 2: v = blurV(t); div; res_next; u ============
// Thread = one x column, 4 consecutive y rows. Recomputes v at the ±1 halo.
__global__ __launch_bounds__(256) void k_vel2(const float* __restrict__ t01,
                                              const float* __restrict__ res,
                                              float* __restrict__ res_next,
                                              __half* __restrict__ res16out,
                                              __half2* __restrict__ uA,
                                              __half2* __restrict__ uB) {
    const int x  = blockIdx.x * 32 + threadIdx.x;
    const int y0 = (blockIdx.y * 8 + threadIdx.y) * 4;
    const int b  = blockIdx.z;
    const float* rp = res + (size_t)b * HW;

    // v at cols x-1..x+1, rows y0-1..y0+4  (out-of-image -> 0; res is 0 there too)
    float v0[3][6], v1[3][6];
    #pragma unroll
    for (int c = 0; c < 3; c++) {
        int cx = x - 1 + c;
        if (cx < 0 || cx >= Ww) {
            #pragma unroll
            for (int r = 0; r < 6; r++) { v0[c][r] = 0.f; v1[c][r] = 0.f; }
            continue;
        }
        float tc0[12], tc1[12];
        #pragma unroll
        for (int r = 0; r < 12; r++) {
            int yy = y0 - 4 + r;
            bool in = (yy >= 0 && yy < Hh);
            int gi = b * HW + yy * Ww + cx;
            tc0[r] = in ? t01[gi] : 0.f;
            tc1[r] = in ? t01[BHW + gi] : 0.f;
        }
        #pragma unroll
        for (int r = 0; r < 6; r++) {
            float s0 = 0.f, s1 = 0.f;
            #pragma unroll
            for (int k = 0; k < 7; k++) {
                s0 += GW[k] * tc0[r + k];
                s1 += GW[k] * tc1[r + k];
            }
            v0[c][r] = s0;
            v1[c][r] = s1;
        }
    }

    // res at cols x-1..x+1, rows y0-1..y0+4 (zero-padded)
    float rs[3][6];
    #pragma unroll
    for (int c = 0; c < 3; c++) {
        int cx = x - 1 + c;
        bool inx = (cx >= 0 && cx < Ww);
        #pragma unroll
        for (int r = 0; r < 6; r++) {
            int yy = y0 - 1 + r;
            rs[c][r] = (inx && yy >= 0 && yy < Hh) ? rp[yy * Ww + cx] : 0.f;
        }
    }

    const float invL = 1.f / (float)Lsteps;
    #pragma unroll
    for (int q = 0; q < 4; q++) {
        int yr = y0 + q;
        int vr = q + 1;   // row yr within the 6-row window (window row 0 = y0-1)
        float f =
            (- rs[0][vr - 1] * v0[0][vr - 1] + rs[2][vr - 1] * v0[2][vr - 1]
             - 2.f * rs[0][vr] * v0[0][vr]   + 2.f * rs[2][vr] * v0[2][vr]
             - rs[0][vr + 1] * v0[0][vr + 1] + rs[2][vr + 1] * v0[2][vr + 1]
             - rs[0][vr - 1] * v1[0][vr - 1] - 2.f * rs[1][vr - 1] * v1[1][vr - 1]
             - rs[2][vr - 1] * v1[2][vr - 1]
             + rs[0][vr + 1] * v1[0][vr + 1] + 2.f * rs[1][vr + 1] * v1[1][vr + 1]
             + rs[2][vr + 1] * v1[2][vr + 1])
            * (0.125f / (float)Lsteps);
        int gidx = b * HW + yr * Ww + x;
        float rv = rs[1][vr] - f;
        res_next[gidx] = rv;
        res16out[gidx] = __float2half(rv);
        __half2 uh = __floats2half2_rn(-v0[1][vr] * invL, -v1[1][vr] * invL);
        uA[gidx] = uh;
        uB[gidx] = uh;
    }
}

// ---------- gather helpers ----------
__device__ __forceinline__ float2 gather_phi(const __half2* __restrict__ u, float px, float py) {
    float x0f = floorf(px), y0f = floorf(py);
    float wx = px - x0f, wy = py - y0f;
    int x0 = (int)x0f, y0 = (int)y0f;
    float w00 = (1.f - wx) * (1.f - wy), w10 = wx * (1.f - wy);
    float w01 = (1.f - wx) * wy,         w11 = wx * wy;
    if (x0 >= 0 && y0 >= 0 && x0 < Ww - 1 && y0 < Hh - 1) {
        const __half2* r0 = u + y0 * Ww + x0;
        float2 a = __half22float2(r0[0]);
        float2 bb = __half22float2(r0[1]);
        float2 c = __half22float2(r0[Ww]);
        float2 d = __half22float2(r0[Ww + 1]);
        float ux = a.x * w00 + bb.x * w10 + c.x * w01 + d.x * w11;
        float uy = a.y * w00 + bb.y * w10 + c.y * w01 + d.y * w11;
        return make_float2(px + ux, py + uy);
    }
    int x1 = x0 + 1, y1 = y0 + 1;
    float rx = 0.f, ry = 0.f;
    #define PHITAP(xt, yt, w) \
        if ((xt) >= 0 && (xt) < Ww && (yt) >= 0 && (yt) < Hh) { \
            float2 uu = __half22float2(u[(yt) * Ww + (xt)]); \
            rx += (w) * ((float)(xt) + uu.x); \
            ry += (w) * ((float)(yt) + uu.y); \
        }
    PHITAP(x0, y0, w00) PHITAP(x1, y0, w10) PHITAP(x0, y1, w01) PHITAP(x1, y1, w11)
    #undef PHITAP
    return make_float2(rx, ry);
}

__device__ __forceinline__ float gather_res16(const __half* __restrict__ p, float px, float py) {
    float x0f = floorf(px), y0f = floorf(py);
    float wx = px - x0f, wy = py - y0f;
    int x0 = (int)x0f, y0 = (int)y0f;
    float Ia, Ib, Ic, Id;
    if (x0 >= 0 && y0 >= 0 && x0 < Ww - 1 && y0 < Hh - 1) {
        const __half* r0 = p + y0 * Ww + x0;
        Ia = __half2float(r0[0]); Ib = __half2float(r0[1]);
        Ic = __half2float(r0[Ww]); Id = __half2float(r0[Ww + 1]);
    } else {
        int x1 = x0 + 1, y1 = y0 + 1;
        bool bx0 = (x0 >= 0) && (x0 < Ww), bx1 = (x1 >= 0) && (x1 < Ww);
        bool by0 = (y0 >= 0) && (y0 < Hh), by1 = (y1 >= 0) && (y1 < Hh);
        Ia = (bx0 && by0) ? __half2float(p[y0 * Ww + x0]) : 0.f;
        Ib = (bx1 && by0) ? __half2float(p[y0 * Ww + x1]) : 0.f;
        Ic = (bx0 && by1) ? __half2float(p[y1 * Ww + x0]) : 0.f;
        Id = (bx1 && by1) ? __half2float(p[y1 * Ww + x1]) : 0.f;
    }
    return Ia * (1.f - wx) * (1.f - wy) + Ib * wx * (1.f - wy)
         + Ic * (1.f - wx) * wy        + Id * wx * wy;
}

__device__ __forceinline__ float bilerp1(const float* __restrict__ p, float px, float py) {
    float x0f = floorf(px), y0f = floorf(py);
    float wx = px - x0f, wy = py - y0f;
    int x0 = (int)x0f, y0 = (int)y0f;
    float Ia, Ib, Ic, Id;
    if (x0 >= 0 && y0 >= 0 && x0 < Ww - 1 && y0 < Hh - 1) {
        const float* r0 = p + y0 * Ww + x0;
        Ia = r0[0]; Ib = r0[1]; Ic = r0[Ww]; Id = r0[Ww + 1];
    } else {
        int x1 = x0 + 1, y1 = y0 + 1;
        bool bx0 = (x0 >= 0) && (x0 < Ww), bx1 = (x1 >= 0) && (x1 < Ww);
        bool by0 = (y0 >= 0) && (y0 < Hh), by1 = (y1 >= 0) && (y1 < Hh);
        Ia = (bx0 && by0) ? p[y0 * Ww + x0] : 0.f;
        Ib = (bx1 && by0) ? p[y0 * Ww + x1] : 0.f;
        Ic = (bx0 && by1) ? p[y1 * Ww + x0] : 0.f;
        Id = (bx1 && by1) ? p[y1 * Ww + x1] : 0.f;
    }
    return Ia * (1.f - wx) * (1.f - wy) + Ib * wx * (1.f - wy)
         + Ic * (1.f - wx) * wy        + Id * wx * wy;
}

// Fused: warp all stored phis through D_i (sampled at pd = D_i(x)), store
// warped displacements, gather residuals, update image.
__global__ void k_warpfinal(int i, const __half2* __restrict__ srcu,
                            __half2* __restrict__ dstu,
                            const float* __restrict__ res32,
                            const __half* __restrict__ res16,
                            const float* __restrict__ srcimg,
                            const float* __restrict__ seg,
                            float* __restrict__ out) {
    int idx = blockIdx.x * blockDim.x + threadIdx.x;
    if (idx >= BHW) return;
    int x = idx & (Ww - 1);
    int y = (idx >> 9) & (Hh - 1);
    int base = idx - (y << 9) - x;
    float fx = (float)x, fy = (float)y;

    float2 ui = __half22float2(srcu[(size_t)i * BHW + idx]);
    float2 pd = make_float2(fx + ui.x, fy + ui.y);

    float acc = res32[(size_t)i * BHW + idx];
    float2 p0 = pd;

    for (int j = 0; j < i; j++) {
        float2 a = gather_phi(srcu + (size_t)j * BHW + base, pd.x, pd.y);
        dstu[(size_t)j * BHW + idx] = __floats2half2_rn(a.x - fx, a.y - fy);
        if (j == 0) p0 = a;
        else acc += gather_res16(res16 + (size_t)(j - 1) * BHW + base, a.x, a.y);
    }
    if (i >= 1) acc += gather_res16(res16 + (size_t)(i - 1) * BHW + base, pd.x, pd.y);

    float s = bilerp1(srcimg + base, p0.x, p0.y);
    float m = bilerp1(seg + base, p0.x, p0.y);
    const float scale = 2.5e-4f;  // MU^2 / L
    out[idx] = s + acc * scale * m;
}

extern "C" void kernel_launch(void* const* d_in, const int* in_sizes, int n_in,
                              void* d_out, int out_size) {
    const float* src = (const float*)d_in[0];
    const float* z0  = (const float*)d_in[1];
    const float* seg = (const float*)d_in[2];

    float*   res;   cudaGetSymbolAddress((void**)&res,   d_res);
    __half*  res16; cudaGetSymbolAddress((void**)&res16, d_res16);
    __half2* uA;    cudaGetSymbolAddress((void**)&uA,    d_uA);
    __half2* uB;    cudaGetSymbolAddress((void**)&uB,    d_uB);
    float*   img;   cudaGetSymbolAddress((void**)&img,   d_img);
    float*   t01;   cudaGetSymbolAddress((void**)&t01,   d_t);

    const int threads = 256;
    const int blocks = BHW / threads;
    dim3 vblk(32, 8);
    dim3 vgrid(Ww / 32, Hh / 32, Bb);

    for (int i = 0; i < Lsteps; i++) {
        const float* img_in = (i == 0) ? src : img;
        const float* res_i  = (i == 0) ? z0  : res + (size_t)(i - 1) * BHW;

        k_vel1<<<vgrid, vblk>>>(img_in, res_i, t01);
        k_vel2<<<vgrid, vblk>>>(t01, res_i, res + (size_t)i * BHW,
                                res16 + (size_t)i * BHW,
                                uA + (size_t)i * BHW, uB + (size_t)i * BHW);

        __half2* dst = (i & 1) ? uB : uA;
        const __half2* s2 = (i & 1) ? uA : uB;
        float* outp = (i == Lsteps - 1) ? (float*)d_out : img;
        k_warpfinal<<<blocks, threads>>>(i, s2, dst, res, res16, src, seg, outp);
    }
}